// round 13
// baseline (speedup 1.0000x reference)
#include <cuda_runtime.h>
#include <cuda_bf16.h>
#include <math_constants.h>
#include <cstdint>

#define N_ROWS  16384       // b*h*w
#define D_DIM   256
#define K_CODES 8192
#define HW      1024
#define ZQ_ELEMS (16 * 256 * 1024)
#define NT      64          // code tiles of 128
#define C1_T    1.25e-6f    // per-row error slope (covers bf16 rounding of z,e)
#define C0_T    1.6e-4f     // fixed slack: fp32 reorder + expr rounding + grid ulps + enorm

// ---------------- scratch ----------------------------------------------------
__device__ __align__(16) float          g_zt[N_ROWS * D_DIM];
__device__ __align__(16) __nv_bfloat16  g_zbf[N_ROWS * D_DIM];
__device__ __align__(16) __nv_bfloat16  g_cbbf[K_CODES * D_DIM];
__device__ float g_znorm[N_ROWS];
__device__ float g_zn1[N_ROWS];
__device__ float g_enorm[K_CODES];
__device__ float g_tmin[N_ROWS * 256];       // per (row, tile, code-quadrant) min
__device__ __align__(16) uint32_t g_mask[N_ROWS * NT * 4];
__device__ int   g_idx[N_ROWS];
__device__ float g_partial[4096];

__device__ __forceinline__ uint32_t smem_u32(const void* p) {
    uint32_t a;
    asm("{ .reg .u64 t; cvta.to.shared.u64 t, %1; cvt.u32.u64 %0, t; }" : "=r"(a) : "l"(p));
    return a;
}
#define LDM4(r, a) \
    asm volatile("ldmatrix.sync.aligned.m8n8.x4.shared.b16 {%0,%1,%2,%3}, [%4];" \
        : "=r"((r)[0]), "=r"((r)[1]), "=r"((r)[2]), "=r"((r)[3]) : "r"(a))
#define MMA16816(d, a, b0, b1) \
    asm volatile("mma.sync.aligned.m16n8k16.row.col.f32.bf16.bf16.f32 " \
        "{%0,%1,%2,%3}, {%4,%5,%6,%7}, {%8,%9}, {%0,%1,%2,%3};" \
        : "+f"((d)[0]), "+f"((d)[1]), "+f"((d)[2]), "+f"((d)[3]) \
        : "r"((a)[0]), "r"((a)[1]), "r"((a)[2]), "r"((a)[3]), "r"(b0), "r"(b1))
#define CP_ASYNC16(s, g) \
    asm volatile("cp.async.cg.shared.global [%0], [%1], 16;" :: "r"(s), "l"(g) : "memory")
#define CP_COMMIT()  asm volatile("cp.async.commit_group;" ::: "memory")
#define CP_WAIT0()   asm volatile("cp.async.wait_group 0;" ::: "memory")

// threshold: identical expression in screen and rescore
__device__ __forceinline__ float t_row(float zn1) {
    return fmaf(zn1, C1_T, C0_T);
}

// ---- kernel 1: fused transpose + bf16 copy + znorm/zn1 ----------------------
__global__ void k_tz(const float* __restrict__ z) {
    __shared__ float t[256][33];
    const int b = blockIdx.y, hw0 = blockIdx.x * 32;
    const int tid = threadIdx.x, w = tid >> 5, lane = tid & 31;
#pragma unroll 8
    for (int it = 0; it < 32; it++) {
        const int idx = it * 256 + tid;
        const int c = idx >> 5, hw = idx & 31;
        t[c][hw] = z[(((size_t)b * 256 + c) << 10) + hw0 + hw];
    }
    __syncthreads();
#pragma unroll
    for (int rr = 0; rr < 4; rr++) {
        const int r = w * 4 + rr;
        const int n = b * HW + hw0 + r;
        float s = 0.f, s1 = 0.f;
#pragma unroll
        for (int i = 0; i < 8; i++) {
            const float v = t[lane + i * 32][r];     // validated serial order
            s  = fmaf(v, v, s);
            s1 += fabsf(v);
        }
#pragma unroll
        for (int o = 16; o; o >>= 1) {
            s  += __shfl_xor_sync(0xffffffffu, s, o);
            s1 += __shfl_xor_sync(0xffffffffu, s1, o);
        }
        if (lane == 0) { g_znorm[n] = s; g_zn1[n] = s1; }
#pragma unroll
        for (int i = 0; i < 8; i++) {
            const int c = lane + i * 32;
            const float v = t[c][r];
            g_zt[(size_t)n * D_DIM + c]  = v;
            g_zbf[(size_t)n * D_DIM + c] = __float2bfloat16_rn(v);
        }
    }
}

// ---------------- kernel 2: codebook -> bf16 + enorm (fused) -----------------
__global__ void k_cbprep(const float* __restrict__ cb) {
    const int warp = (blockIdx.x * 256 + threadIdx.x) >> 5;
    const int lane = threadIdx.x & 31;
    const float* src = cb + (size_t)warp * D_DIM;
    float s = 0.f;
#pragma unroll
    for (int i = 0; i < 8; i++) {
        float v = src[lane + i * 32];
        s = fmaf(v, v, s);
    }
#pragma unroll
    for (int o = 16; o; o >>= 1) s += __shfl_xor_sync(0xffffffffu, s, o);
    if (lane == 0) g_enorm[warp] = s;

    float4 v0 = *(const float4*)(src + lane * 8);
    float4 v1 = *(const float4*)(src + lane * 8 + 4);
    __nv_bfloat162 p0{__float2bfloat16_rn(v0.x), __float2bfloat16_rn(v0.y)};
    __nv_bfloat162 p1{__float2bfloat16_rn(v0.z), __float2bfloat16_rn(v0.w)};
    __nv_bfloat162 p2{__float2bfloat16_rn(v1.x), __float2bfloat16_rn(v1.y)};
    __nv_bfloat162 p3{__float2bfloat16_rn(v1.z), __float2bfloat16_rn(v1.w)};
    uint4 o;
    o.x = *(uint32_t*)&p0; o.y = *(uint32_t*)&p1;
    o.z = *(uint32_t*)&p2; o.w = *(uint32_t*)&p3;
    *(uint4*)(g_cbbf + (size_t)warp * D_DIM + lane * 8) = o;
}

// ---------------- kernel 3: HMMA bf16 screen GEMM + per-warp min/mask --------
#define SM_A    0
#define SM_B0   65536
#define SM_B1   131072
#define SMEM_TOTAL 196608

__device__ __forceinline__ void stage_async(const __nv_bfloat16* __restrict__ g,
                                            uint32_t sdst, int tid) {
#pragma unroll
    for (int it = 0; it < 8; it++) {
        const int idx = it * 512 + tid;
        const int row = idx >> 5, ch = idx & 31;
        CP_ASYNC16(sdst + row * 512 + ((ch ^ (row & 7)) << 4),
                   g + (size_t)row * 256 + ch * 8);
    }
}

__global__ __launch_bounds__(512, 1) void k_screen() {
    extern __shared__ char smem[];
    const int tid = threadIdx.x, w = tid >> 5, lane = tid & 31;
    const int wm = (w >> 2) * 32, wc = w & 3, wn = wc * 32;
    const int gid = lane >> 2, tg = lane & 3, ls = lane & 7;
    const int row0 = blockIdx.x * 128;
    const uint32_t sb = smem_u32(smem);

    stage_async(g_zbf + (size_t)row0 * D_DIM, sb + SM_A, tid);
    stage_async(g_cbbf, sb + SM_B0, tid);
    CP_COMMIT();

    int rows[4]; float znr[4], Trw[4];
#pragma unroll
    for (int k = 0; k < 4; k++) {
        const int r = wm + (k >> 1) * 16 + (k & 1) * 8 + gid;
        rows[k] = r;
        znr[k]  = g_znorm[row0 + r];
        Trw[k]  = t_row(g_zn1[row0 + r]);
    }

    const int kmA = lane >> 4;
    const int kmB = (lane >> 3) & 1;
    uint32_t baA[2];
#pragma unroll
    for (int i = 0; i < 2; i++) {
        const int r = wm + i * 16 + ((lane >> 3) & 1) * 8 + ls;
        baA[i] = sb + SM_A + r * 512;
    }
    uint32_t boff[2];
#pragma unroll
    for (int p = 0; p < 2; p++) {
        const int r = wn + (p * 2 + (lane >> 4)) * 8 + ls;
        boff[p] = r * 512;
    }

    float acc[2][4][4];
#pragma unroll
    for (int i = 0; i < 2; i++)
#pragma unroll
        for (int j = 0; j < 4; j++)
#pragma unroll
            for (int c = 0; c < 4; c++) acc[i][j][c] = 0.f;

    CP_WAIT0();
    __syncthreads();

    for (int t = 0; t < NT; t++) {
        const uint32_t bbase = sb + ((t & 1) ? SM_B1 : SM_B0);
        if (t + 1 < NT) {
            stage_async(g_cbbf + (size_t)(t + 1) * 128 * D_DIM,
                        sb + (((t + 1) & 1) ? SM_B1 : SM_B0), tid);
            CP_COMMIT();
        }
#pragma unroll 4
        for (int kc = 0; kc < 16; kc++) {
            uint32_t a[2][4], bq[2][4];
            const uint32_t offA = (uint32_t)(((2 * kc + kmA) ^ ls) << 4);
            const uint32_t offB = (uint32_t)(((2 * kc + kmB) ^ ls) << 4);
            LDM4(a[0], baA[0] + offA);
            LDM4(a[1], baA[1] + offA);
            LDM4(bq[0], bbase + boff[0] + offB);
            LDM4(bq[1], bbase + boff[1] + offB);
#pragma unroll
            for (int i = 0; i < 2; i++)
#pragma unroll
                for (int j = 0; j < 4; j++)
                    MMA16816(acc[i][j], a[i], bq[j >> 1][(j & 1) * 2],
                             bq[j >> 1][(j & 1) * 2 + 1]);
        }

        // ---- all-register epilogue: per-warp min + superset mask (no enorm) ----
        float rmin[4] = {CUDART_INF_F, CUDART_INF_F, CUDART_INF_F, CUDART_INF_F};
#pragma unroll
        for (int i = 0; i < 2; i++)
#pragma unroll
            for (int j = 0; j < 4; j++)
#pragma unroll
                for (int c = 0; c < 4; c++) {
                    const int k = i * 2 + (c >> 1);
                    const float s = fmaf(-2.f, acc[i][j][c], znr[k]);
                    rmin[k] = fminf(rmin[k], s);
                }
#pragma unroll
        for (int k = 0; k < 4; k++) {
            rmin[k] = fminf(rmin[k], __shfl_xor_sync(0xffffffffu, rmin[k], 1));
            rmin[k] = fminf(rmin[k], __shfl_xor_sync(0xffffffffu, rmin[k], 2));
        }
        uint32_t m[4] = {0, 0, 0, 0};
#pragma unroll
        for (int i = 0; i < 2; i++)
#pragma unroll
            for (int j = 0; j < 4; j++)
#pragma unroll
                for (int c = 0; c < 4; c++) {
                    const int k = i * 2 + (c >> 1);
                    const float s = fmaf(-2.f, acc[i][j][c], znr[k]);
                    if (s < rmin[k] + Trw[k]) m[k] |= 1u << (j * 8 + tg * 2 + (c & 1));
                }
#pragma unroll
        for (int k = 0; k < 4; k++) {
            m[k] |= __shfl_xor_sync(0xffffffffu, m[k], 1);
            m[k] |= __shfl_xor_sync(0xffffffffu, m[k], 2);
        }
        if (tg == 0) {
#pragma unroll
            for (int k = 0; k < 4; k++) {
                g_mask[((size_t)(row0 + rows[k]) * NT + t) * 4 + wc] = m[k];
                g_tmin[(size_t)(row0 + rows[k]) * 256 + t * 4 + wc]  = rmin[k];
            }
        }
#pragma unroll
        for (int i = 0; i < 2; i++)
#pragma unroll
            for (int j = 0; j < 4; j++)
#pragma unroll
                for (int c = 0; c < 4; c++) acc[i][j][c] = 0.f;
        CP_WAIT0();
        __syncthreads();
    }
}

// ---- kernel 4: exact fp32 rescore — warp per row, zero block barriers -------
__global__ __launch_bounds__(256) void k_rescore(const float* __restrict__ cb,
                                                 float* __restrict__ oidx) {
    __shared__ float zs[8][256];
    const int wid = threadIdx.x >> 5, lane = threadIdx.x & 31;
    const int row = blockIdx.x * 8 + wid;
    float* zrow = zs[wid];

    // stage zrow (per-warp, coalesced)
#pragma unroll
    for (int i = 0; i < 8; i++)
        zrow[lane + i * 32] = g_zt[(size_t)row * D_DIM + lane + i * 32];

    // per-lane: 2 tiles (t = lane, lane+32), 4 quadrant mins each
    const float4 tmA = ((const float4*)g_tmin)[row * 64 + lane];
    const float4 tmB = ((const float4*)g_tmin)[row * 64 + lane + 32];
    float mn = fminf(fminf(fminf(tmA.x, tmA.y), fminf(tmA.z, tmA.w)),
                     fminf(fminf(tmB.x, tmB.y), fminf(tmB.z, tmB.w)));
#pragma unroll
    for (int o = 16; o; o >>= 1)
        mn = fminf(mn, __shfl_xor_sync(0xffffffffu, mn, o));

    const float Trow = t_row(g_zn1[row]);
    const float zn   = g_znorm[row];
    const float th   = mn + Trow;
    __syncwarp();

    float bd = CUDART_INF_F; int bi = 0x7fffffff;
#pragma unroll
    for (int half = 0; half < 2; half++) {
        const int t = lane + half * 32;
        const float4 tm4 = half ? tmB : tmA;
        const float tmv[4] = {tm4.x, tm4.y, tm4.z, tm4.w};
#pragma unroll
        for (int q = 0; q < 4; q++) {
            if (tmv[q] < th) {
                uint32_t bits = g_mask[((size_t)row * NT + t) * 4 + q];
                while (bits) {
                    const int j = __ffs(bits) - 1; bits &= bits - 1;
                    const int k = t * 128 + q * 32 + j;
                    const float4* e4 = (const float4*)(cb + (size_t)k * D_DIM);
                    // double-buffered chunk loads; fmaf order d0=0..255 UNCHANGED
                    float4 buf0[8], buf1[8];
#pragma unroll
                    for (int i = 0; i < 8; i++) buf0[i] = __ldg(e4 + i);
                    float acc = 0.f;
#pragma unroll
                    for (int ch = 0; ch < 8; ch++) {
                        const float4* cur = (ch & 1) ? buf1 : buf0;
                        float4*       nxt = (ch & 1) ? buf0 : buf1;
                        if (ch < 7) {
#pragma unroll
                            for (int i = 0; i < 8; i++)
                                nxt[i] = __ldg(e4 + (ch + 1) * 8 + i);
                        }
#pragma unroll
                        for (int i = 0; i < 8; i++) {
                            const int d0 = ch * 32 + i * 4;
                            acc = fmaf(zrow[d0],     cur[i].x, acc);
                            acc = fmaf(zrow[d0 + 1], cur[i].y, acc);
                            acc = fmaf(zrow[d0 + 2], cur[i].z, acc);
                            acc = fmaf(zrow[d0 + 3], cur[i].w, acc);
                        }
                    }
                    const float s   = zn + __ldg(&g_enorm[k]);
                    const float dsc = s - 2.0f * acc;
                    if (dsc < bd || (dsc == bd && k < bi)) { bd = dsc; bi = k; }
                }
            }
        }
    }
    // warp lexicographic (d, idx) min
#pragma unroll
    for (int o = 16; o; o >>= 1) {
        const float d2 = __shfl_xor_sync(0xffffffffu, bd, o);
        const int   i2 = __shfl_xor_sync(0xffffffffu, bi, o);
        if (d2 < bd || (d2 == bd && i2 < bi)) { bd = d2; bi = i2; }
    }
    if (lane == 0) { g_idx[row] = bi; oidx[row] = (float)bi; }
}

// ---------------- kernel 5: gather + straight-through + loss partials --------
__global__ void k_gather(const float* __restrict__ z, const float* __restrict__ cb,
                         float* __restrict__ out) {
    const int c = blockIdx.x, b = blockIdx.y;
    const float* zp = z   + ((size_t)b * D_DIM + c) * HW;
    float*       op = out + ((size_t)b * D_DIM + c) * HW;
    float part = 0.f;
#pragma unroll
    for (int it = 0; it < 4; it++) {
        const int hw  = it * 256 + threadIdx.x;
        const int idx = g_idx[b * HW + hw];
        float q  = __ldg(cb + (size_t)idx * D_DIM + c);
        float zv = zp[hw];
        float t  = q - zv;
        op[hw]   = zv + t;
        part     = fmaf(t, t, part);
    }
    __shared__ float sm[8];
    const int lane = threadIdx.x & 31, ww = threadIdx.x >> 5;
#pragma unroll
    for (int o = 16; o; o >>= 1) part += __shfl_xor_sync(0xffffffffu, part, o);
    if (lane == 0) sm[ww] = part;
    __syncthreads();
    if (threadIdx.x == 0) {
        float s = 0.f;
        for (int i = 0; i < 8; i++) s += sm[i];
        g_partial[b * 256 + c] = s;
    }
}

// ---------------- kernel 6: loss finalize ------------------------------------
__global__ void k_loss(float* __restrict__ out) {
    __shared__ float sm[256];
    const int tid = threadIdx.x;
    float s = 0.f;
#pragma unroll
    for (int i = 0; i < 16; i++) s += g_partial[tid * 16 + i];
    sm[tid] = s;
    __syncthreads();
    for (int o = 128; o; o >>= 1) {
        if (tid < o) sm[tid] += sm[tid + o];
        __syncthreads();
    }
    if (tid == 0) {
        const float m = sm[0] / (float)ZQ_ELEMS;
        out[ZQ_ELEMS] = m + 0.25f * m;
    }
}

// ---------------- launcher ---------------------------------------------------
extern "C" void kernel_launch(void* const* d_in, const int* in_sizes, int n_in,
                              void* d_out, int out_size) {
    const float* z  = (const float*)d_in[0];
    const float* cb = (const float*)d_in[1];
    float* out = (float*)d_out;

    static int attr_set = 0;
    if (!attr_set) {
        cudaFuncSetAttribute(k_screen, cudaFuncAttributeMaxDynamicSharedMemorySize,
                             SMEM_TOTAL);
        attr_set = 1;
    }

    dim3 gT(32, 16);
    k_tz<<<gT, 256>>>(z);
    k_cbprep<<<1024, 256>>>(cb);
    k_screen<<<128, 512, SMEM_TOTAL>>>();
    k_rescore<<<N_ROWS / 8, 256>>>(cb, out + ZQ_ELEMS + 1);
    dim3 gG(256, 16);
    k_gather<<<gG, 256>>>(z, cb, out);
    k_loss<<<1, 256>>>(out);
}

// round 14
// speedup vs baseline: 1.1163x; 1.1163x over previous
#include <cuda_runtime.h>
#include <cuda_bf16.h>
#include <math_constants.h>
#include <cstdint>

#define N_ROWS  16384       // b*h*w
#define D_DIM   256
#define K_CODES 8192
#define HW      1024
#define ZQ_ELEMS (16 * 256 * 1024)
#define NT      64          // code tiles of 128
#define C1_T    1.25e-6f    // per-row error slope (covers bf16 rounding of z,e)
#define C0_T    1.6e-4f     // fixed slack: fp32 reorder + expr rounding + grid ulps + enorm

// ---------------- scratch ----------------------------------------------------
__device__ __align__(16) float          g_zt[N_ROWS * D_DIM];
__device__ __align__(16) __nv_bfloat16  g_zbf[N_ROWS * D_DIM];
__device__ __align__(16) __nv_bfloat16  g_cbbf[K_CODES * D_DIM];
__device__ float g_znorm[N_ROWS];
__device__ float g_zn1[N_ROWS];
__device__ float g_enorm[K_CODES];
__device__ float g_tmin[N_ROWS * 256];       // per (row, tile, code-quadrant) min
__device__ __align__(16) uint32_t g_mask[N_ROWS * NT * 4];
__device__ int   g_idx[N_ROWS];
__device__ float g_partial[4096];

__device__ __forceinline__ uint32_t smem_u32(const void* p) {
    uint32_t a;
    asm("{ .reg .u64 t; cvta.to.shared.u64 t, %1; cvt.u32.u64 %0, t; }" : "=r"(a) : "l"(p));
    return a;
}
#define LDM4(r, a) \
    asm volatile("ldmatrix.sync.aligned.m8n8.x4.shared.b16 {%0,%1,%2,%3}, [%4];" \
        : "=r"((r)[0]), "=r"((r)[1]), "=r"((r)[2]), "=r"((r)[3]) : "r"(a))
#define MMA16816(d, a, b0, b1) \
    asm volatile("mma.sync.aligned.m16n8k16.row.col.f32.bf16.bf16.f32 " \
        "{%0,%1,%2,%3}, {%4,%5,%6,%7}, {%8,%9}, {%0,%1,%2,%3};" \
        : "+f"((d)[0]), "+f"((d)[1]), "+f"((d)[2]), "+f"((d)[3]) \
        : "r"((a)[0]), "r"((a)[1]), "r"((a)[2]), "r"((a)[3]), "r"(b0), "r"(b1))
#define CP_ASYNC16(s, g) \
    asm volatile("cp.async.cg.shared.global [%0], [%1], 16;" :: "r"(s), "l"(g) : "memory")
#define CP_COMMIT()  asm volatile("cp.async.commit_group;" ::: "memory")
#define CP_WAIT0()   asm volatile("cp.async.wait_group 0;" ::: "memory")

// threshold: identical expression in screen and rescore
__device__ __forceinline__ float t_row(float zn1) {
    return fmaf(zn1, C1_T, C0_T);
}

// exact candidate score: serial fmaf d0=0..255, double-buffered loads
__device__ __forceinline__ float cand_score(const float* __restrict__ zrow,
                                            const float* __restrict__ cb,
                                            int k, float zn) {
    const float4* e4 = (const float4*)(cb + (size_t)k * D_DIM);
    float4 buf0[8], buf1[8];
#pragma unroll
    for (int i = 0; i < 8; i++) buf0[i] = __ldg(e4 + i);
    float acc = 0.f;
#pragma unroll
    for (int ch = 0; ch < 8; ch++) {
        const float4* cur = (ch & 1) ? buf1 : buf0;
        float4*       nxt = (ch & 1) ? buf0 : buf1;
        if (ch < 7) {
#pragma unroll
            for (int i = 0; i < 8; i++) nxt[i] = __ldg(e4 + (ch + 1) * 8 + i);
        }
#pragma unroll
        for (int i = 0; i < 8; i++) {
            const int d0 = ch * 32 + i * 4;
            acc = fmaf(zrow[d0],     cur[i].x, acc);
            acc = fmaf(zrow[d0 + 1], cur[i].y, acc);
            acc = fmaf(zrow[d0 + 2], cur[i].z, acc);
            acc = fmaf(zrow[d0 + 3], cur[i].w, acc);
        }
    }
    const float s = zn + __ldg(&g_enorm[k]);
    return s - 2.0f * acc;
}

// ---- kernel 1: fused transpose + bf16 copy + znorm/zn1 ----------------------
__global__ void k_tz(const float* __restrict__ z) {
    __shared__ float t[256][33];
    const int b = blockIdx.y, hw0 = blockIdx.x * 32;
    const int tid = threadIdx.x, w = tid >> 5, lane = tid & 31;
#pragma unroll 8
    for (int it = 0; it < 32; it++) {
        const int idx = it * 256 + tid;
        const int c = idx >> 5, hw = idx & 31;
        t[c][hw] = z[(((size_t)b * 256 + c) << 10) + hw0 + hw];
    }
    __syncthreads();
#pragma unroll
    for (int rr = 0; rr < 4; rr++) {
        const int r = w * 4 + rr;
        const int n = b * HW + hw0 + r;
        float s = 0.f, s1 = 0.f;
#pragma unroll
        for (int i = 0; i < 8; i++) {
            const float v = t[lane + i * 32][r];     // validated serial order
            s  = fmaf(v, v, s);
            s1 += fabsf(v);
        }
#pragma unroll
        for (int o = 16; o; o >>= 1) {
            s  += __shfl_xor_sync(0xffffffffu, s, o);
            s1 += __shfl_xor_sync(0xffffffffu, s1, o);
        }
        if (lane == 0) { g_znorm[n] = s; g_zn1[n] = s1; }
#pragma unroll
        for (int i = 0; i < 8; i++) {
            const int c = lane + i * 32;
            const float v = t[c][r];
            g_zt[(size_t)n * D_DIM + c]  = v;
            g_zbf[(size_t)n * D_DIM + c] = __float2bfloat16_rn(v);
        }
    }
}

// ---------------- kernel 2: codebook -> bf16 + enorm (fused) -----------------
__global__ void k_cbprep(const float* __restrict__ cb) {
    const int warp = (blockIdx.x * 256 + threadIdx.x) >> 5;
    const int lane = threadIdx.x & 31;
    const float* src = cb + (size_t)warp * D_DIM;
    float s = 0.f;
#pragma unroll
    for (int i = 0; i < 8; i++) {
        float v = src[lane + i * 32];
        s = fmaf(v, v, s);
    }
#pragma unroll
    for (int o = 16; o; o >>= 1) s += __shfl_xor_sync(0xffffffffu, s, o);
    if (lane == 0) g_enorm[warp] = s;

    float4 v0 = *(const float4*)(src + lane * 8);
    float4 v1 = *(const float4*)(src + lane * 8 + 4);
    __nv_bfloat162 p0{__float2bfloat16_rn(v0.x), __float2bfloat16_rn(v0.y)};
    __nv_bfloat162 p1{__float2bfloat16_rn(v0.z), __float2bfloat16_rn(v0.w)};
    __nv_bfloat162 p2{__float2bfloat16_rn(v1.x), __float2bfloat16_rn(v1.y)};
    __nv_bfloat162 p3{__float2bfloat16_rn(v1.z), __float2bfloat16_rn(v1.w)};
    uint4 o;
    o.x = *(uint32_t*)&p0; o.y = *(uint32_t*)&p1;
    o.z = *(uint32_t*)&p2; o.w = *(uint32_t*)&p3;
    *(uint4*)(g_cbbf + (size_t)warp * D_DIM + lane * 8) = o;
}

// ---------------- kernel 3: HMMA bf16 screen GEMM + per-warp min/mask --------
#define SM_A    0
#define SM_B0   65536
#define SM_B1   131072
#define SMEM_TOTAL 196608

__device__ __forceinline__ void stage_async(const __nv_bfloat16* __restrict__ g,
                                            uint32_t sdst, int tid) {
#pragma unroll
    for (int it = 0; it < 8; it++) {
        const int idx = it * 512 + tid;
        const int row = idx >> 5, ch = idx & 31;
        CP_ASYNC16(sdst + row * 512 + ((ch ^ (row & 7)) << 4),
                   g + (size_t)row * 256 + ch * 8);
    }
}

__global__ __launch_bounds__(512, 1) void k_screen() {
    extern __shared__ char smem[];
    const int tid = threadIdx.x, w = tid >> 5, lane = tid & 31;
    const int wm = (w >> 2) * 32, wc = w & 3, wn = wc * 32;
    const int gid = lane >> 2, tg = lane & 3, ls = lane & 7;
    const int row0 = blockIdx.x * 128;
    const uint32_t sb = smem_u32(smem);

    stage_async(g_zbf + (size_t)row0 * D_DIM, sb + SM_A, tid);
    stage_async(g_cbbf, sb + SM_B0, tid);
    CP_COMMIT();

    int rows[4]; float znr[4], Trw[4];
#pragma unroll
    for (int k = 0; k < 4; k++) {
        const int r = wm + (k >> 1) * 16 + (k & 1) * 8 + gid;
        rows[k] = r;
        znr[k]  = g_znorm[row0 + r];
        Trw[k]  = t_row(g_zn1[row0 + r]);
    }

    const int kmA = lane >> 4;
    const int kmB = (lane >> 3) & 1;
    uint32_t baA[2];
#pragma unroll
    for (int i = 0; i < 2; i++) {
        const int r = wm + i * 16 + ((lane >> 3) & 1) * 8 + ls;
        baA[i] = sb + SM_A + r * 512;
    }
    uint32_t boff[2];
#pragma unroll
    for (int p = 0; p < 2; p++) {
        const int r = wn + (p * 2 + (lane >> 4)) * 8 + ls;
        boff[p] = r * 512;
    }

    float acc[2][4][4];
#pragma unroll
    for (int i = 0; i < 2; i++)
#pragma unroll
        for (int j = 0; j < 4; j++)
#pragma unroll
            for (int c = 0; c < 4; c++) acc[i][j][c] = 0.f;

    CP_WAIT0();
    __syncthreads();

    for (int t = 0; t < NT; t++) {
        const uint32_t bbase = sb + ((t & 1) ? SM_B1 : SM_B0);
        if (t + 1 < NT) {
            stage_async(g_cbbf + (size_t)(t + 1) * 128 * D_DIM,
                        sb + (((t + 1) & 1) ? SM_B1 : SM_B0), tid);
            CP_COMMIT();
        }
#pragma unroll 4
        for (int kc = 0; kc < 16; kc++) {
            uint32_t a[2][4], bq[2][4];
            const uint32_t offA = (uint32_t)(((2 * kc + kmA) ^ ls) << 4);
            const uint32_t offB = (uint32_t)(((2 * kc + kmB) ^ ls) << 4);
            LDM4(a[0], baA[0] + offA);
            LDM4(a[1], baA[1] + offA);
            LDM4(bq[0], bbase + boff[0] + offB);
            LDM4(bq[1], bbase + boff[1] + offB);
#pragma unroll
            for (int i = 0; i < 2; i++)
#pragma unroll
                for (int j = 0; j < 4; j++)
                    MMA16816(acc[i][j], a[i], bq[j >> 1][(j & 1) * 2],
                             bq[j >> 1][(j & 1) * 2 + 1]);
        }

        // ---- all-register epilogue: per-warp min + superset mask (no enorm) ----
        float rmin[4] = {CUDART_INF_F, CUDART_INF_F, CUDART_INF_F, CUDART_INF_F};
#pragma unroll
        for (int i = 0; i < 2; i++)
#pragma unroll
            for (int j = 0; j < 4; j++)
#pragma unroll
                for (int c = 0; c < 4; c++) {
                    const int k = i * 2 + (c >> 1);
                    const float s = fmaf(-2.f, acc[i][j][c], znr[k]);
                    rmin[k] = fminf(rmin[k], s);
                }
#pragma unroll
        for (int k = 0; k < 4; k++) {
            rmin[k] = fminf(rmin[k], __shfl_xor_sync(0xffffffffu, rmin[k], 1));
            rmin[k] = fminf(rmin[k], __shfl_xor_sync(0xffffffffu, rmin[k], 2));
        }
        uint32_t m[4] = {0, 0, 0, 0};
#pragma unroll
        for (int i = 0; i < 2; i++)
#pragma unroll
            for (int j = 0; j < 4; j++)
#pragma unroll
                for (int c = 0; c < 4; c++) {
                    const int k = i * 2 + (c >> 1);
                    const float s = fmaf(-2.f, acc[i][j][c], znr[k]);
                    if (s < rmin[k] + Trw[k]) m[k] |= 1u << (j * 8 + tg * 2 + (c & 1));
                }
#pragma unroll
        for (int k = 0; k < 4; k++) {
            m[k] |= __shfl_xor_sync(0xffffffffu, m[k], 1);
            m[k] |= __shfl_xor_sync(0xffffffffu, m[k], 2);
        }
        if (tg == 0) {
#pragma unroll
            for (int k = 0; k < 4; k++) {
                g_mask[((size_t)(row0 + rows[k]) * NT + t) * 4 + wc] = m[k];
                g_tmin[(size_t)(row0 + rows[k]) * 256 + t * 4 + wc]  = rmin[k];
            }
        }
#pragma unroll
        for (int i = 0; i < 2; i++)
#pragma unroll
            for (int j = 0; j < 4; j++)
#pragma unroll
                for (int c = 0; c < 4; c++) acc[i][j][c] = 0.f;
        CP_WAIT0();
        __syncthreads();
    }
}

// ---- kernel 4: candidate-parallel exact rescore (32 rows / block) -----------
#define RROWS 32
#define LISTMAX 2048
__global__ __launch_bounds__(256) void k_rescore(const float* __restrict__ cb,
                                                 float* __restrict__ oidx) {
    __shared__ float zs[RROWS][257];
    __shared__ unsigned long long keys[RROWS];
    __shared__ float znS[RROWS];
    __shared__ int   list[LISTMAX];
    __shared__ int   cnt;
    const int tid = threadIdx.x, w = tid >> 5, lane = tid & 31;
    const int rowbase = blockIdx.x * RROWS;

    // stage zrows (coalesced), init keys/cnt
    for (int idx = tid; idx < RROWS * 256; idx += 256)
        zs[idx >> 8][idx & 255] = g_zt[(size_t)(rowbase + (idx >> 8)) * D_DIM + (idx & 255)];
    if (tid < RROWS) keys[tid] = ~0ull;
    if (tid == 0) cnt = 0;
    __syncthreads();

    // phase 1: per warp, 4 rows — threshold + candidate gather
#pragma unroll 1
    for (int rr = 0; rr < 4; rr++) {
        const int rl  = w * 4 + rr;
        const int row = rowbase + rl;
        const float4 tmA = ((const float4*)g_tmin)[row * 64 + lane];
        const float4 tmB = ((const float4*)g_tmin)[row * 64 + lane + 32];
        float mn = fminf(fminf(fminf(tmA.x, tmA.y), fminf(tmA.z, tmA.w)),
                         fminf(fminf(tmB.x, tmB.y), fminf(tmB.z, tmB.w)));
#pragma unroll
        for (int o = 16; o; o >>= 1)
            mn = fminf(mn, __shfl_xor_sync(0xffffffffu, mn, o));
        const float zn = g_znorm[row];
        const float th = mn + t_row(g_zn1[row]);
        if (lane == 0) znS[rl] = zn;
        const float tmv[8] = {tmA.x, tmA.y, tmA.z, tmA.w, tmB.x, tmB.y, tmB.z, tmB.w};
#pragma unroll
        for (int hq = 0; hq < 8; hq++) {
            if (tmv[hq] < th) {
                const int t = lane + (hq >> 2) * 32, q = hq & 3;
                uint32_t bits = g_mask[((size_t)row * NT + t) * 4 + q];
                while (bits) {
                    const int j = __ffs(bits) - 1; bits &= bits - 1;
                    const int k = t * 128 + q * 32 + j;
                    const int pos = atomicAdd(&cnt, 1);
                    if (pos < LISTMAX) {
                        list[pos] = (rl << 13) | k;
                    } else {
                        // overflow fallback (never expected): compute inline
                        const float dsc = cand_score(zs[rl], cb, k, zn);
                        const unsigned long long key =
                            ((unsigned long long)__float_as_uint(dsc) << 32) | (uint32_t)k;
                        atomicMin(&keys[rl], key);
                    }
                }
            }
        }
    }
    __syncthreads();

    // phase 2: one candidate per thread (exact serial dot, unchanged order)
    const int total = (cnt < LISTMAX) ? cnt : LISTMAX;
    for (int idx = tid; idx < total; idx += 256) {
        const int e  = list[idx];
        const int rl = e >> 13, k = e & 8191;
        const float dsc = cand_score(zs[rl], cb, k, znS[rl]);
        const unsigned long long key =
            ((unsigned long long)__float_as_uint(dsc) << 32) | (uint32_t)k;
        atomicMin(&keys[rl], key);
    }
    __syncthreads();

    if (tid < RROWS) {
        const int bi = (int)(keys[tid] & 0xFFFFFFFFull);
        g_idx[rowbase + tid] = bi;
        oidx[rowbase + tid]  = (float)bi;
    }
}

// ---------------- kernel 5: gather + straight-through + loss partials --------
__global__ void k_gather(const float* __restrict__ z, const float* __restrict__ cb,
                         float* __restrict__ out) {
    const int c = blockIdx.x, b = blockIdx.y;
    const float* zp = z   + ((size_t)b * D_DIM + c) * HW;
    float*       op = out + ((size_t)b * D_DIM + c) * HW;
    float part = 0.f;
#pragma unroll
    for (int it = 0; it < 4; it++) {
        const int hw  = it * 256 + threadIdx.x;
        const int idx = g_idx[b * HW + hw];
        float q  = __ldg(cb + (size_t)idx * D_DIM + c);
        float zv = zp[hw];
        float t  = q - zv;
        op[hw]   = zv + t;
        part     = fmaf(t, t, part);
    }
    __shared__ float sm[8];
    const int lane = threadIdx.x & 31, ww = threadIdx.x >> 5;
#pragma unroll
    for (int o = 16; o; o >>= 1) part += __shfl_xor_sync(0xffffffffu, part, o);
    if (lane == 0) sm[ww] = part;
    __syncthreads();
    if (threadIdx.x == 0) {
        float s = 0.f;
        for (int i = 0; i < 8; i++) s += sm[i];
        g_partial[b * 256 + c] = s;
    }
}

// ---------------- kernel 6: loss finalize ------------------------------------
__global__ void k_loss(float* __restrict__ out) {
    __shared__ float sm[256];
    const int tid = threadIdx.x;
    float s = 0.f;
#pragma unroll
    for (int i = 0; i < 16; i++) s += g_partial[tid * 16 + i];
    sm[tid] = s;
    __syncthreads();
    for (int o = 128; o; o >>= 1) {
        if (tid < o) sm[tid] += sm[tid + o];
        __syncthreads();
    }
    if (tid == 0) {
        const float m = sm[0] / (float)ZQ_ELEMS;
        out[ZQ_ELEMS] = m + 0.25f * m;
    }
}

// ---------------- launcher ---------------------------------------------------
extern "C" void kernel_launch(void* const* d_in, const int* in_sizes, int n_in,
                              void* d_out, int out_size) {
    const float* z  = (const float*)d_in[0];
    const float* cb = (const float*)d_in[1];
    float* out = (float*)d_out;

    static int attr_set = 0;
    if (!attr_set) {
        cudaFuncSetAttribute(k_screen, cudaFuncAttributeMaxDynamicSharedMemorySize,
                             SMEM_TOTAL);
        attr_set = 1;
    }

    dim3 gT(32, 16);
    k_tz<<<gT, 256>>>(z);
    k_cbprep<<<1024, 256>>>(cb);
    k_screen<<<128, 512, SMEM_TOTAL>>>();
    k_rescore<<<N_ROWS / RROWS, 256>>>(cb, out + ZQ_ELEMS + 1);
    dim3 gG(256, 16);
    k_gather<<<gG, 256>>>(z, cb, out);
    k_loss<<<1, 256>>>(out);
}

// round 15
// speedup vs baseline: 1.1387x; 1.0201x over previous
#include <cuda_runtime.h>
#include <cuda_bf16.h>
#include <math_constants.h>
#include <cstdint>

#define N_ROWS  16384       // b*h*w
#define D_DIM   256
#define K_CODES 8192
#define HW      1024
#define ZQ_ELEMS (16 * 256 * 1024)
#define NT      64          // code tiles of 128
#define C1_T    1.25e-6f    // per-row error slope (covers bf16 rounding of z,e)
#define C0_T    1.6e-4f     // fixed slack: fp32 reorder + expr rounding + grid ulps + enorm

// ---------------- scratch ----------------------------------------------------
__device__ __align__(16) float          g_zt[N_ROWS * D_DIM];
__device__ __align__(16) __nv_bfloat16  g_zbf[N_ROWS * D_DIM];
__device__ __align__(16) __nv_bfloat16  g_cbbf[K_CODES * D_DIM];
__device__ float g_znorm[N_ROWS];
__device__ float g_zn1[N_ROWS];
__device__ float g_enorm[K_CODES];
__device__ float g_tmin[N_ROWS * 256];       // per (row, tile, code-quadrant) min
__device__ __align__(16) uint32_t g_mask[N_ROWS * NT * 4];
__device__ int   g_idx[N_ROWS];
__device__ float g_partial[4096];

__device__ __forceinline__ uint32_t smem_u32(const void* p) {
    uint32_t a;
    asm("{ .reg .u64 t; cvta.to.shared.u64 t, %1; cvt.u32.u64 %0, t; }" : "=r"(a) : "l"(p));
    return a;
}
#define LDM4(r, a) \
    asm volatile("ldmatrix.sync.aligned.m8n8.x4.shared.b16 {%0,%1,%2,%3}, [%4];" \
        : "=r"((r)[0]), "=r"((r)[1]), "=r"((r)[2]), "=r"((r)[3]) : "r"(a))
#define MMA16816(d, a, b0, b1) \
    asm volatile("mma.sync.aligned.m16n8k16.row.col.f32.bf16.bf16.f32 " \
        "{%0,%1,%2,%3}, {%4,%5,%6,%7}, {%8,%9}, {%0,%1,%2,%3};" \
        : "+f"((d)[0]), "+f"((d)[1]), "+f"((d)[2]), "+f"((d)[3]) \
        : "r"((a)[0]), "r"((a)[1]), "r"((a)[2]), "r"((a)[3]), "r"(b0), "r"(b1))
#define CP_ASYNC16(s, g) \
    asm volatile("cp.async.cg.shared.global [%0], [%1], 16;" :: "r"(s), "l"(g) : "memory")
#define CP_COMMIT()  asm volatile("cp.async.commit_group;" ::: "memory")
#define CP_WAIT0()   asm volatile("cp.async.wait_group 0;" ::: "memory")

// threshold: identical expression in screen and rescore
__device__ __forceinline__ float t_row(float zn1) {
    return fmaf(zn1, C1_T, C0_T);
}

// exact candidate score: serial fmaf d0=0..255, double-buffered loads
__device__ __forceinline__ float cand_score(const float* __restrict__ zrow,
                                            const float* __restrict__ cb,
                                            int k, float zn) {
    const float4* e4 = (const float4*)(cb + (size_t)k * D_DIM);
    float4 buf0[8], buf1[8];
#pragma unroll
    for (int i = 0; i < 8; i++) buf0[i] = __ldg(e4 + i);
    float acc = 0.f;
#pragma unroll
    for (int ch = 0; ch < 8; ch++) {
        const float4* cur = (ch & 1) ? buf1 : buf0;
        float4*       nxt = (ch & 1) ? buf0 : buf1;
        if (ch < 7) {
#pragma unroll
            for (int i = 0; i < 8; i++) nxt[i] = __ldg(e4 + (ch + 1) * 8 + i);
        }
#pragma unroll
        for (int i = 0; i < 8; i++) {
            const int d0 = ch * 32 + i * 4;
            acc = fmaf(zrow[d0],     cur[i].x, acc);
            acc = fmaf(zrow[d0 + 1], cur[i].y, acc);
            acc = fmaf(zrow[d0 + 2], cur[i].z, acc);
            acc = fmaf(zrow[d0 + 3], cur[i].w, acc);
        }
    }
    const float s = zn + __ldg(&g_enorm[k]);
    return s - 2.0f * acc;
}

// ---- kernel 1: fused transpose + bf16 copy + znorm/zn1 ----------------------
__global__ void k_tz(const float* __restrict__ z) {
    __shared__ float t[256][33];
    const int b = blockIdx.y, hw0 = blockIdx.x * 32;
    const int tid = threadIdx.x, w = tid >> 5, lane = tid & 31;
#pragma unroll 8
    for (int it = 0; it < 32; it++) {
        const int idx = it * 256 + tid;
        const int c = idx >> 5, hw = idx & 31;
        t[c][hw] = z[(((size_t)b * 256 + c) << 10) + hw0 + hw];
    }
    __syncthreads();
#pragma unroll
    for (int rr = 0; rr < 4; rr++) {
        const int r = w * 4 + rr;
        const int n = b * HW + hw0 + r;
        float s = 0.f, s1 = 0.f;
#pragma unroll
        for (int i = 0; i < 8; i++) {
            const float v = t[lane + i * 32][r];     // validated serial order
            s  = fmaf(v, v, s);
            s1 += fabsf(v);
        }
#pragma unroll
        for (int o = 16; o; o >>= 1) {
            s  += __shfl_xor_sync(0xffffffffu, s, o);
            s1 += __shfl_xor_sync(0xffffffffu, s1, o);
        }
        if (lane == 0) { g_znorm[n] = s; g_zn1[n] = s1; }
#pragma unroll
        for (int i = 0; i < 8; i++) {
            const int c = lane + i * 32;
            const float v = t[c][r];
            g_zt[(size_t)n * D_DIM + c]  = v;
            g_zbf[(size_t)n * D_DIM + c] = __float2bfloat16_rn(v);
        }
    }
}

// ---------------- kernel 2: codebook -> bf16 + enorm (fused) -----------------
__global__ void k_cbprep(const float* __restrict__ cb) {
    const int warp = (blockIdx.x * 256 + threadIdx.x) >> 5;
    const int lane = threadIdx.x & 31;
    const float* src = cb + (size_t)warp * D_DIM;
    float s = 0.f;
#pragma unroll
    for (int i = 0; i < 8; i++) {
        float v = src[lane + i * 32];
        s = fmaf(v, v, s);
    }
#pragma unroll
    for (int o = 16; o; o >>= 1) s += __shfl_xor_sync(0xffffffffu, s, o);
    if (lane == 0) g_enorm[warp] = s;

    float4 v0 = *(const float4*)(src + lane * 8);
    float4 v1 = *(const float4*)(src + lane * 8 + 4);
    __nv_bfloat162 p0{__float2bfloat16_rn(v0.x), __float2bfloat16_rn(v0.y)};
    __nv_bfloat162 p1{__float2bfloat16_rn(v0.z), __float2bfloat16_rn(v0.w)};
    __nv_bfloat162 p2{__float2bfloat16_rn(v1.x), __float2bfloat16_rn(v1.y)};
    __nv_bfloat162 p3{__float2bfloat16_rn(v1.z), __float2bfloat16_rn(v1.w)};
    uint4 o;
    o.x = *(uint32_t*)&p0; o.y = *(uint32_t*)&p1;
    o.z = *(uint32_t*)&p2; o.w = *(uint32_t*)&p3;
    *(uint4*)(g_cbbf + (size_t)warp * D_DIM + lane * 8) = o;
}

// ---------------- kernel 3: HMMA bf16 screen GEMM + per-warp min/mask --------
#define SM_A    0
#define SM_B0   65536
#define SM_B1   131072
#define SMEM_TOTAL 196608

__device__ __forceinline__ void stage_async(const __nv_bfloat16* __restrict__ g,
                                            uint32_t sdst, int tid) {
#pragma unroll
    for (int it = 0; it < 8; it++) {
        const int idx = it * 512 + tid;
        const int row = idx >> 5, ch = idx & 31;
        CP_ASYNC16(sdst + row * 512 + ((ch ^ (row & 7)) << 4),
                   g + (size_t)row * 256 + ch * 8);
    }
}

__global__ __launch_bounds__(512, 1) void k_screen() {
    extern __shared__ char smem[];
    const int tid = threadIdx.x, w = tid >> 5, lane = tid & 31;
    const int wm = (w >> 2) * 32, wc = w & 3, wn = wc * 32;
    const int gid = lane >> 2, tg = lane & 3, ls = lane & 7;
    const int row0 = blockIdx.x * 128;
    const uint32_t sb = smem_u32(smem);

    stage_async(g_zbf + (size_t)row0 * D_DIM, sb + SM_A, tid);
    stage_async(g_cbbf, sb + SM_B0, tid);
    CP_COMMIT();

    int rows[4]; float znr[4], Trw[4];
#pragma unroll
    for (int k = 0; k < 4; k++) {
        const int r = wm + (k >> 1) * 16 + (k & 1) * 8 + gid;
        rows[k] = r;
        znr[k]  = g_znorm[row0 + r];
        Trw[k]  = t_row(g_zn1[row0 + r]);
    }

    const int kmA = lane >> 4;
    const int kmB = (lane >> 3) & 1;
    uint32_t baA[2];
#pragma unroll
    for (int i = 0; i < 2; i++) {
        const int r = wm + i * 16 + ((lane >> 3) & 1) * 8 + ls;
        baA[i] = sb + SM_A + r * 512;
    }
    uint32_t boff[2];
#pragma unroll
    for (int p = 0; p < 2; p++) {
        const int r = wn + (p * 2 + (lane >> 4)) * 8 + ls;
        boff[p] = r * 512;
    }

    float acc[2][4][4];
#pragma unroll
    for (int i = 0; i < 2; i++)
#pragma unroll
        for (int j = 0; j < 4; j++)
#pragma unroll
            for (int c = 0; c < 4; c++) acc[i][j][c] = 0.f;

    CP_WAIT0();
    __syncthreads();

    for (int t = 0; t < NT; t++) {
        const uint32_t bbase = sb + ((t & 1) ? SM_B1 : SM_B0);
        if (t + 1 < NT) {
            stage_async(g_cbbf + (size_t)(t + 1) * 128 * D_DIM,
                        sb + (((t + 1) & 1) ? SM_B1 : SM_B0), tid);
            CP_COMMIT();
        }
#pragma unroll 4
        for (int kc = 0; kc < 16; kc++) {
            uint32_t a[2][4], bq[2][4];
            const uint32_t offA = (uint32_t)(((2 * kc + kmA) ^ ls) << 4);
            const uint32_t offB = (uint32_t)(((2 * kc + kmB) ^ ls) << 4);
            LDM4(a[0], baA[0] + offA);
            LDM4(a[1], baA[1] + offA);
            LDM4(bq[0], bbase + boff[0] + offB);
            LDM4(bq[1], bbase + boff[1] + offB);
#pragma unroll
            for (int i = 0; i < 2; i++)
#pragma unroll
                for (int j = 0; j < 4; j++)
                    MMA16816(acc[i][j], a[i], bq[j >> 1][(j & 1) * 2],
                             bq[j >> 1][(j & 1) * 2 + 1]);
        }

        // ---- all-register epilogue: per-warp min + superset mask (no enorm) ----
        float rmin[4] = {CUDART_INF_F, CUDART_INF_F, CUDART_INF_F, CUDART_INF_F};
#pragma unroll
        for (int i = 0; i < 2; i++)
#pragma unroll
            for (int j = 0; j < 4; j++)
#pragma unroll
                for (int c = 0; c < 4; c++) {
                    const int k = i * 2 + (c >> 1);
                    const float s = fmaf(-2.f, acc[i][j][c], znr[k]);
                    rmin[k] = fminf(rmin[k], s);
                }
#pragma unroll
        for (int k = 0; k < 4; k++) {
            rmin[k] = fminf(rmin[k], __shfl_xor_sync(0xffffffffu, rmin[k], 1));
            rmin[k] = fminf(rmin[k], __shfl_xor_sync(0xffffffffu, rmin[k], 2));
        }
        uint32_t m[4] = {0, 0, 0, 0};
#pragma unroll
        for (int i = 0; i < 2; i++)
#pragma unroll
            for (int j = 0; j < 4; j++)
#pragma unroll
                for (int c = 0; c < 4; c++) {
                    const int k = i * 2 + (c >> 1);
                    const float s = fmaf(-2.f, acc[i][j][c], znr[k]);
                    if (s < rmin[k] + Trw[k]) m[k] |= 1u << (j * 8 + tg * 2 + (c & 1));
                }
#pragma unroll
        for (int k = 0; k < 4; k++) {
            m[k] |= __shfl_xor_sync(0xffffffffu, m[k], 1);
            m[k] |= __shfl_xor_sync(0xffffffffu, m[k], 2);
        }
        if (tg == 0) {
#pragma unroll
            for (int k = 0; k < 4; k++) {
                g_mask[((size_t)(row0 + rows[k]) * NT + t) * 4 + wc] = m[k];
                g_tmin[(size_t)(row0 + rows[k]) * 256 + t * 4 + wc]  = rmin[k];
            }
        }
#pragma unroll
        for (int i = 0; i < 2; i++)
#pragma unroll
            for (int j = 0; j < 4; j++)
#pragma unroll
                for (int c = 0; c < 4; c++) acc[i][j][c] = 0.f;
        CP_WAIT0();
        __syncthreads();
    }
}

// ---- kernel 4: candidate-parallel exact rescore (16 rows / block) -----------
#define RROWS 16
#define LISTMAX 1024
__global__ __launch_bounds__(256) void k_rescore(const float* __restrict__ cb,
                                                 float* __restrict__ oidx) {
    __shared__ float zs[RROWS][257];
    __shared__ unsigned long long keys[RROWS];
    __shared__ float znS[RROWS];
    __shared__ int   list[LISTMAX];
    __shared__ int   cnt;
    const int tid = threadIdx.x, w = tid >> 5, lane = tid & 31;
    const int rowbase = blockIdx.x * RROWS;

    // stage zrows (float4, coalesced): 16 rows x 64 float4 = 1024 loads
#pragma unroll
    for (int it = 0; it < 4; it++) {
        const int idx = it * 256 + tid;            // 0..1023
        const int r = idx >> 6, c4 = idx & 63;
        const float4 v = __ldg((const float4*)(g_zt + (size_t)(rowbase + r) * D_DIM) + c4);
        zs[r][c4 * 4]     = v.x;
        zs[r][c4 * 4 + 1] = v.y;
        zs[r][c4 * 4 + 2] = v.z;
        zs[r][c4 * 4 + 3] = v.w;
    }
    if (tid < RROWS) keys[tid] = ~0ull;
    if (tid == 0) cnt = 0;
    __syncthreads();

    // phase 1: per warp, 2 rows — threshold + candidate gather
#pragma unroll 1
    for (int rr = 0; rr < 2; rr++) {
        const int rl  = w * 2 + rr;
        const int row = rowbase + rl;
        const float4 tmA = ((const float4*)g_tmin)[row * 64 + lane];
        const float4 tmB = ((const float4*)g_tmin)[row * 64 + lane + 32];
        float mn = fminf(fminf(fminf(tmA.x, tmA.y), fminf(tmA.z, tmA.w)),
                         fminf(fminf(tmB.x, tmB.y), fminf(tmB.z, tmB.w)));
#pragma unroll
        for (int o = 16; o; o >>= 1)
            mn = fminf(mn, __shfl_xor_sync(0xffffffffu, mn, o));
        const float zn = g_znorm[row];
        const float th = mn + t_row(g_zn1[row]);
        if (lane == 0) znS[rl] = zn;
        const float tmv[8] = {tmA.x, tmA.y, tmA.z, tmA.w, tmB.x, tmB.y, tmB.z, tmB.w};
#pragma unroll
        for (int hq = 0; hq < 8; hq++) {
            if (tmv[hq] < th) {
                const int t = lane + (hq >> 2) * 32, q = hq & 3;
                uint32_t bits = g_mask[((size_t)row * NT + t) * 4 + q];
                while (bits) {
                    const int j = __ffs(bits) - 1; bits &= bits - 1;
                    const int k = t * 128 + q * 32 + j;
                    const int pos = atomicAdd(&cnt, 1);
                    if (pos < LISTMAX) {
                        list[pos] = (rl << 13) | k;
                    } else {
                        // overflow fallback (never expected): compute inline
                        const float dsc = cand_score(zs[rl], cb, k, zn);
                        const unsigned long long key =
                            ((unsigned long long)__float_as_uint(dsc) << 32) | (uint32_t)k;
                        atomicMin(&keys[rl], key);
                    }
                }
            }
        }
    }
    __syncthreads();

    // phase 2: one candidate per thread (exact serial dot, unchanged order)
    const int total = (cnt < LISTMAX) ? cnt : LISTMAX;
    for (int idx = tid; idx < total; idx += 256) {
        const int e  = list[idx];
        const int rl = e >> 13, k = e & 8191;
        const float dsc = cand_score(zs[rl], cb, k, znS[rl]);
        const unsigned long long key =
            ((unsigned long long)__float_as_uint(dsc) << 32) | (uint32_t)k;
        atomicMin(&keys[rl], key);
    }
    __syncthreads();

    if (tid < RROWS) {
        const int bi = (int)(keys[tid] & 0xFFFFFFFFull);
        g_idx[rowbase + tid] = bi;
        oidx[rowbase + tid]  = (float)bi;
    }
}

// ---------------- kernel 5: gather + straight-through + loss partials --------
__global__ void k_gather(const float* __restrict__ z, const float* __restrict__ cb,
                         float* __restrict__ out) {
    const int c = blockIdx.x, b = blockIdx.y;
    const float* zp = z   + ((size_t)b * D_DIM + c) * HW;
    float*       op = out + ((size_t)b * D_DIM + c) * HW;
    float part = 0.f;
#pragma unroll
    for (int it = 0; it < 4; it++) {
        const int hw  = it * 256 + threadIdx.x;
        const int idx = g_idx[b * HW + hw];
        float q  = __ldg(cb + (size_t)idx * D_DIM + c);
        float zv = zp[hw];
        float t  = q - zv;
        op[hw]   = zv + t;
        part     = fmaf(t, t, part);
    }
    __shared__ float sm[8];
    const int lane = threadIdx.x & 31, ww = threadIdx.x >> 5;
#pragma unroll
    for (int o = 16; o; o >>= 1) part += __shfl_xor_sync(0xffffffffu, part, o);
    if (lane == 0) sm[ww] = part;
    __syncthreads();
    if (threadIdx.x == 0) {
        float s = 0.f;
        for (int i = 0; i < 8; i++) s += sm[i];
        g_partial[b * 256 + c] = s;
    }
}

// ---------------- kernel 6: loss finalize ------------------------------------
__global__ void k_loss(float* __restrict__ out) {
    __shared__ float sm[256];
    const int tid = threadIdx.x;
    float s = 0.f;
#pragma unroll
    for (int i = 0; i < 16; i++) s += g_partial[tid * 16 + i];
    sm[tid] = s;
    __syncthreads();
    for (int o = 128; o; o >>= 1) {
        if (tid < o) sm[tid] += sm[tid + o];
        __syncthreads();
    }
    if (tid == 0) {
        const float m = sm[0] / (float)ZQ_ELEMS;
        out[ZQ_ELEMS] = m + 0.25f * m;
    }
}

// ---------------- launcher ---------------------------------------------------
extern "C" void kernel_launch(void* const* d_in, const int* in_sizes, int n_in,
                              void* d_out, int out_size) {
    const float* z  = (const float*)d_in[0];
    const float* cb = (const float*)d_in[1];
    float* out = (float*)d_out;

    static int attr_set = 0;
    if (!attr_set) {
        cudaFuncSetAttribute(k_screen, cudaFuncAttributeMaxDynamicSharedMemorySize,
                             SMEM_TOTAL);
        attr_set = 1;
    }

    dim3 gT(32, 16);
    k_tz<<<gT, 256>>>(z);
    k_cbprep<<<1024, 256>>>(cb);
    k_screen<<<128, 512, SMEM_TOTAL>>>();
    k_rescore<<<N_ROWS / RROWS, 256>>>(cb, out + ZQ_ELEMS + 1);
    dim3 gG(256, 16);
    k_gather<<<gG, 256>>>(z, cb, out);
    k_loss<<<1, 256>>>(out);
}

// round 16
// speedup vs baseline: 1.2247x; 1.0756x over previous
#include <cuda_runtime.h>
#include <cuda_bf16.h>
#include <math_constants.h>
#include <cstdint>

#define N_ROWS  16384       // b*h*w
#define D_DIM   256
#define K_CODES 8192
#define HW      1024
#define ZQ_ELEMS (16 * 256 * 1024)
#define NT      64          // code tiles of 128
#define NSM     148
#define NJOBS   (128 * 64)  // row-tiles x code-tiles
#define C1_T    1.25e-6f    // per-row error slope (covers bf16 rounding of z,e)
#define C0_T    1.6e-4f     // fixed slack: fp32 reorder + expr rounding + grid ulps + enorm

// ---------------- scratch ----------------------------------------------------
__device__ __align__(16) float          g_zt[N_ROWS * D_DIM];
__device__ __align__(16) __nv_bfloat16  g_zbf[N_ROWS * D_DIM];
__device__ __align__(16) __nv_bfloat16  g_cbbf[K_CODES * D_DIM];
__device__ float g_znorm[N_ROWS];
__device__ float g_zn1[N_ROWS];
__device__ float g_enorm[K_CODES];
__device__ float g_tmin[N_ROWS * 256];       // per (row, tile, code-quadrant) min
__device__ __align__(16) uint32_t g_mask[N_ROWS * NT * 4];
__device__ int   g_idx[N_ROWS];
__device__ float g_partial[4096];

__device__ __forceinline__ uint32_t smem_u32(const void* p) {
    uint32_t a;
    asm("{ .reg .u64 t; cvta.to.shared.u64 t, %1; cvt.u32.u64 %0, t; }" : "=r"(a) : "l"(p));
    return a;
}
#define LDM4(r, a) \
    asm volatile("ldmatrix.sync.aligned.m8n8.x4.shared.b16 {%0,%1,%2,%3}, [%4];" \
        : "=r"((r)[0]), "=r"((r)[1]), "=r"((r)[2]), "=r"((r)[3]) : "r"(a))
#define MMA16816(d, a, b0, b1) \
    asm volatile("mma.sync.aligned.m16n8k16.row.col.f32.bf16.bf16.f32 " \
        "{%0,%1,%2,%3}, {%4,%5,%6,%7}, {%8,%9}, {%0,%1,%2,%3};" \
        : "+f"((d)[0]), "+f"((d)[1]), "+f"((d)[2]), "+f"((d)[3]) \
        : "r"((a)[0]), "r"((a)[1]), "r"((a)[2]), "r"((a)[3]), "r"(b0), "r"(b1))
#define CP_ASYNC16(s, g) \
    asm volatile("cp.async.cg.shared.global [%0], [%1], 16;" :: "r"(s), "l"(g) : "memory")
#define CP_COMMIT()  asm volatile("cp.async.commit_group;" ::: "memory")
#define CP_WAIT0()   asm volatile("cp.async.wait_group 0;" ::: "memory")

// threshold: identical expression in screen and rescore
__device__ __forceinline__ float t_row(float zn1) {
    return fmaf(zn1, C1_T, C0_T);
}

// exact candidate score: serial fmaf d0=0..255, double-buffered loads
__device__ __forceinline__ float cand_score(const float* __restrict__ zrow,
                                            const float* __restrict__ cb,
                                            int k, float zn) {
    const float4* e4 = (const float4*)(cb + (size_t)k * D_DIM);
    float4 buf0[8], buf1[8];
#pragma unroll
    for (int i = 0; i < 8; i++) buf0[i] = __ldg(e4 + i);
    float acc = 0.f;
#pragma unroll
    for (int ch = 0; ch < 8; ch++) {
        const float4* cur = (ch & 1) ? buf1 : buf0;
        float4*       nxt = (ch & 1) ? buf0 : buf1;
        if (ch < 7) {
#pragma unroll
            for (int i = 0; i < 8; i++) nxt[i] = __ldg(e4 + (ch + 1) * 8 + i);
        }
#pragma unroll
        for (int i = 0; i < 8; i++) {
            const int d0 = ch * 32 + i * 4;
            acc = fmaf(zrow[d0],     cur[i].x, acc);
            acc = fmaf(zrow[d0 + 1], cur[i].y, acc);
            acc = fmaf(zrow[d0 + 2], cur[i].z, acc);
            acc = fmaf(zrow[d0 + 3], cur[i].w, acc);
        }
    }
    const float s = zn + __ldg(&g_enorm[k]);
    return s - 2.0f * acc;
}

// ---- kernel 1: fused transpose + bf16 copy + znorm/zn1 ----------------------
__global__ void k_tz(const float* __restrict__ z) {
    __shared__ float t[256][33];
    const int b = blockIdx.y, hw0 = blockIdx.x * 32;
    const int tid = threadIdx.x, w = tid >> 5, lane = tid & 31;
#pragma unroll 8
    for (int it = 0; it < 32; it++) {
        const int idx = it * 256 + tid;
        const int c = idx >> 5, hw = idx & 31;
        t[c][hw] = z[(((size_t)b * 256 + c) << 10) + hw0 + hw];
    }
    __syncthreads();
#pragma unroll
    for (int rr = 0; rr < 4; rr++) {
        const int r = w * 4 + rr;
        const int n = b * HW + hw0 + r;
        float s = 0.f, s1 = 0.f;
#pragma unroll
        for (int i = 0; i < 8; i++) {
            const float v = t[lane + i * 32][r];     // validated serial order
            s  = fmaf(v, v, s);
            s1 += fabsf(v);
        }
#pragma unroll
        for (int o = 16; o; o >>= 1) {
            s  += __shfl_xor_sync(0xffffffffu, s, o);
            s1 += __shfl_xor_sync(0xffffffffu, s1, o);
        }
        if (lane == 0) { g_znorm[n] = s; g_zn1[n] = s1; }
#pragma unroll
        for (int i = 0; i < 8; i++) {
            const int c = lane + i * 32;
            const float v = t[c][r];
            g_zt[(size_t)n * D_DIM + c]  = v;
            g_zbf[(size_t)n * D_DIM + c] = __float2bfloat16_rn(v);
        }
    }
}

// ---------------- kernel 2: codebook -> bf16 + enorm (fused) -----------------
__global__ void k_cbprep(const float* __restrict__ cb) {
    const int warp = (blockIdx.x * 256 + threadIdx.x) >> 5;
    const int lane = threadIdx.x & 31;
    const float* src = cb + (size_t)warp * D_DIM;
    float s = 0.f;
#pragma unroll
    for (int i = 0; i < 8; i++) {
        float v = src[lane + i * 32];
        s = fmaf(v, v, s);
    }
#pragma unroll
    for (int o = 16; o; o >>= 1) s += __shfl_xor_sync(0xffffffffu, s, o);
    if (lane == 0) g_enorm[warp] = s;

    float4 v0 = *(const float4*)(src + lane * 8);
    float4 v1 = *(const float4*)(src + lane * 8 + 4);
    __nv_bfloat162 p0{__float2bfloat16_rn(v0.x), __float2bfloat16_rn(v0.y)};
    __nv_bfloat162 p1{__float2bfloat16_rn(v0.z), __float2bfloat16_rn(v0.w)};
    __nv_bfloat162 p2{__float2bfloat16_rn(v1.x), __float2bfloat16_rn(v1.y)};
    __nv_bfloat162 p3{__float2bfloat16_rn(v1.z), __float2bfloat16_rn(v1.w)};
    uint4 o;
    o.x = *(uint32_t*)&p0; o.y = *(uint32_t*)&p1;
    o.z = *(uint32_t*)&p2; o.w = *(uint32_t*)&p3;
    *(uint4*)(g_cbbf + (size_t)warp * D_DIM + lane * 8) = o;
}

// ---- kernel 3: HMMA screen, 148 persistent CTAs over 8192 (rt, ct) jobs -----
#define SM_A    0
#define SM_B0   65536
#define SM_B1   131072
#define SMEM_TOTAL 196608

__device__ __forceinline__ void stage_async(const __nv_bfloat16* __restrict__ g,
                                            uint32_t sdst, int tid) {
#pragma unroll
    for (int it = 0; it < 8; it++) {
        const int idx = it * 512 + tid;
        const int row = idx >> 5, ch = idx & 31;
        CP_ASYNC16(sdst + row * 512 + ((ch ^ (row & 7)) << 4),
                   g + (size_t)row * 256 + ch * 8);
    }
}

__global__ __launch_bounds__(512, 1) void k_screen() {
    extern __shared__ char smem[];
    const int tid = threadIdx.x, w = tid >> 5, lane = tid & 31;
    const int wm = (w >> 2) * 32, wc = w & 3, wn = wc * 32;
    const int gid = lane >> 2, tg = lane & 3, ls = lane & 7;
    const uint32_t sb = smem_u32(smem);

    const int jstart = (blockIdx.x * NJOBS) / NSM;
    const int jend   = ((blockIdx.x + 1) * NJOBS) / NSM;

    int rt   = jstart >> 6;
    int row0 = rt << 7;

    stage_async(g_zbf + (size_t)row0 * D_DIM, sb + SM_A, tid);
    stage_async(g_cbbf + (size_t)(jstart & 63) * 128 * D_DIM, sb + SM_B0, tid);
    CP_COMMIT();

    int rows[4]; float znr[4], Trw[4];
#pragma unroll
    for (int k = 0; k < 4; k++) {
        const int r = wm + (k >> 1) * 16 + (k & 1) * 8 + gid;
        rows[k] = r;
        znr[k]  = g_znorm[row0 + r];
        Trw[k]  = t_row(g_zn1[row0 + r]);
    }

    const int kmA = lane >> 4;
    const int kmB = (lane >> 3) & 1;
    uint32_t baA[2];
#pragma unroll
    for (int i = 0; i < 2; i++) {
        const int r = wm + i * 16 + ((lane >> 3) & 1) * 8 + ls;
        baA[i] = sb + SM_A + r * 512;
    }
    uint32_t boff[2];
#pragma unroll
    for (int p = 0; p < 2; p++) {
        const int r = wn + (p * 2 + (lane >> 4)) * 8 + ls;
        boff[p] = r * 512;
    }

    float acc[2][4][4];
#pragma unroll
    for (int i = 0; i < 2; i++)
#pragma unroll
        for (int j = 0; j < 4; j++)
#pragma unroll
            for (int c = 0; c < 4; c++) acc[i][j][c] = 0.f;

    CP_WAIT0();
    __syncthreads();

    int pb = 0;
    for (int j = jstart; j < jend; j++) {
        const int ct = j & 63;
        const uint32_t bbase = sb + (pb ? SM_B1 : SM_B0);
        const bool nb = (j + 1 < jend);
        const int rtn = (j + 1) >> 6;
        if (nb) {
            stage_async(g_cbbf + (size_t)((j + 1) & 63) * 128 * D_DIM,
                        sb + (pb ? SM_B0 : SM_B1), tid);
            CP_COMMIT();
        }
#pragma unroll 4
        for (int kc = 0; kc < 16; kc++) {
            uint32_t a[2][4], bq[2][4];
            const uint32_t offA = (uint32_t)(((2 * kc + kmA) ^ ls) << 4);
            const uint32_t offB = (uint32_t)(((2 * kc + kmB) ^ ls) << 4);
            LDM4(a[0], baA[0] + offA);
            LDM4(a[1], baA[1] + offA);
            LDM4(bq[0], bbase + boff[0] + offB);
            LDM4(bq[1], bbase + boff[1] + offB);
#pragma unroll
            for (int i = 0; i < 2; i++)
#pragma unroll
                for (int jj = 0; jj < 4; jj++)
                    MMA16816(acc[i][jj], a[i], bq[jj >> 1][(jj & 1) * 2],
                             bq[jj >> 1][(jj & 1) * 2 + 1]);
        }

        // row-tile switch: all warps done reading SM_A -> restage A (overlaps epilogue)
        const bool sw = nb && (rtn != rt);
        if (sw) {
            __syncthreads();
            stage_async(g_zbf + (size_t)(rtn << 7) * D_DIM, sb + SM_A, tid);
            CP_COMMIT();
        }

        // ---- all-register epilogue: per-warp min + superset mask (no enorm) ----
        float rmin[4] = {CUDART_INF_F, CUDART_INF_F, CUDART_INF_F, CUDART_INF_F};
#pragma unroll
        for (int i = 0; i < 2; i++)
#pragma unroll
            for (int jj = 0; jj < 4; jj++)
#pragma unroll
                for (int c = 0; c < 4; c++) {
                    const int k = i * 2 + (c >> 1);
                    const float s = fmaf(-2.f, acc[i][jj][c], znr[k]);
                    rmin[k] = fminf(rmin[k], s);
                }
#pragma unroll
        for (int k = 0; k < 4; k++) {
            rmin[k] = fminf(rmin[k], __shfl_xor_sync(0xffffffffu, rmin[k], 1));
            rmin[k] = fminf(rmin[k], __shfl_xor_sync(0xffffffffu, rmin[k], 2));
        }
        uint32_t m[4] = {0, 0, 0, 0};
#pragma unroll
        for (int i = 0; i < 2; i++)
#pragma unroll
            for (int jj = 0; jj < 4; jj++)
#pragma unroll
                for (int c = 0; c < 4; c++) {
                    const int k = i * 2 + (c >> 1);
                    const float s = fmaf(-2.f, acc[i][jj][c], znr[k]);
                    if (s < rmin[k] + Trw[k]) m[k] |= 1u << (jj * 8 + tg * 2 + (c & 1));
                }
#pragma unroll
        for (int k = 0; k < 4; k++) {
            m[k] |= __shfl_xor_sync(0xffffffffu, m[k], 1);
            m[k] |= __shfl_xor_sync(0xffffffffu, m[k], 2);
        }
        if (tg == 0) {
#pragma unroll
            for (int k = 0; k < 4; k++) {
                g_mask[((size_t)(row0 + rows[k]) * NT + ct) * 4 + wc] = m[k];
                g_tmin[(size_t)(row0 + rows[k]) * 256 + ct * 4 + wc]  = rmin[k];
            }
        }
#pragma unroll
        for (int i = 0; i < 2; i++)
#pragma unroll
            for (int jj = 0; jj < 4; jj++)
#pragma unroll
                for (int c = 0; c < 4; c++) acc[i][jj][c] = 0.f;

        if (sw) {
            rt = rtn; row0 = rt << 7;
#pragma unroll
            for (int k = 0; k < 4; k++) {
                znr[k] = g_znorm[row0 + rows[k]];
                Trw[k] = t_row(g_zn1[row0 + rows[k]]);
            }
        }
        CP_WAIT0();
        __syncthreads();
        pb ^= 1;
    }
}

// ---- kernel 4: candidate-parallel exact rescore (16 rows / block) -----------
#define RROWS 16
#define LISTMAX 1024
__global__ __launch_bounds__(256) void k_rescore(const float* __restrict__ cb,
                                                 float* __restrict__ oidx) {
    __shared__ float zs[RROWS][257];
    __shared__ unsigned long long keys[RROWS];
    __shared__ float znS[RROWS];
    __shared__ int   list[LISTMAX];
    __shared__ int   cnt;
    const int tid = threadIdx.x, w = tid >> 5, lane = tid & 31;
    const int rowbase = blockIdx.x * RROWS;

    // stage zrows (float4, coalesced)
#pragma unroll
    for (int it = 0; it < 4; it++) {
        const int idx = it * 256 + tid;
        const int r = idx >> 6, c4 = idx & 63;
        const float4 v = __ldg((const float4*)(g_zt + (size_t)(rowbase + r) * D_DIM) + c4);
        zs[r][c4 * 4]     = v.x;
        zs[r][c4 * 4 + 1] = v.y;
        zs[r][c4 * 4 + 2] = v.z;
        zs[r][c4 * 4 + 3] = v.w;
    }
    if (tid < RROWS) keys[tid] = ~0ull;
    if (tid == 0) cnt = 0;
    __syncthreads();

    // phase 1: per warp, 2 rows — threshold + candidate gather
#pragma unroll 1
    for (int rr = 0; rr < 2; rr++) {
        const int rl  = w * 2 + rr;
        const int row = rowbase + rl;
        const float4 tmA = ((const float4*)g_tmin)[row * 64 + lane];
        const float4 tmB = ((const float4*)g_tmin)[row * 64 + lane + 32];
        float mn = fminf(fminf(fminf(tmA.x, tmA.y), fminf(tmA.z, tmA.w)),
                         fminf(fminf(tmB.x, tmB.y), fminf(tmB.z, tmB.w)));
#pragma unroll
        for (int o = 16; o; o >>= 1)
            mn = fminf(mn, __shfl_xor_sync(0xffffffffu, mn, o));
        const float zn = g_znorm[row];
        const float th = mn + t_row(g_zn1[row]);
        if (lane == 0) znS[rl] = zn;
        const float tmv[8] = {tmA.x, tmA.y, tmA.z, tmA.w, tmB.x, tmB.y, tmB.z, tmB.w};
#pragma unroll
        for (int hq = 0; hq < 8; hq++) {
            if (tmv[hq] < th) {
                const int t = lane + (hq >> 2) * 32, q = hq & 3;
                uint32_t bits = g_mask[((size_t)row * NT + t) * 4 + q];
                while (bits) {
                    const int j = __ffs(bits) - 1; bits &= bits - 1;
                    const int k = t * 128 + q * 32 + j;
                    const int pos = atomicAdd(&cnt, 1);
                    if (pos < LISTMAX) {
                        list[pos] = (rl << 13) | k;
                    } else {
                        const float dsc = cand_score(zs[rl], cb, k, zn);
                        const unsigned long long key =
                            ((unsigned long long)__float_as_uint(dsc) << 32) | (uint32_t)k;
                        atomicMin(&keys[rl], key);
                    }
                }
            }
        }
    }
    __syncthreads();

    // phase 2: one candidate per thread (exact serial dot, unchanged order)
    const int total = (cnt < LISTMAX) ? cnt : LISTMAX;
    for (int idx = tid; idx < total; idx += 256) {
        const int e  = list[idx];
        const int rl = e >> 13, k = e & 8191;
        const float dsc = cand_score(zs[rl], cb, k, znS[rl]);
        const unsigned long long key =
            ((unsigned long long)__float_as_uint(dsc) << 32) | (uint32_t)k;
        atomicMin(&keys[rl], key);
    }
    __syncthreads();

    if (tid < RROWS) {
        const int bi = (int)(keys[tid] & 0xFFFFFFFFull);
        g_idx[rowbase + tid] = bi;
        oidx[rowbase + tid]  = (float)bi;
    }
}

// ---------------- kernel 5: gather + straight-through + loss partials --------
__global__ void k_gather(const float* __restrict__ z, const float* __restrict__ cb,
                         float* __restrict__ out) {
    const int c = blockIdx.x, b = blockIdx.y;
    const float* zp = z   + ((size_t)b * D_DIM + c) * HW;
    float*       op = out + ((size_t)b * D_DIM + c) * HW;
    float part = 0.f;
#pragma unroll
    for (int it = 0; it < 4; it++) {
        const int hw  = it * 256 + threadIdx.x;
        const int idx = g_idx[b * HW + hw];
        float q  = __ldg(cb + (size_t)idx * D_DIM + c);
        float zv = zp[hw];
        float t  = q - zv;
        op[hw]   = zv + t;
        part     = fmaf(t, t, part);
    }
    __shared__ float sm[8];
    const int lane = threadIdx.x & 31, ww = threadIdx.x >> 5;
#pragma unroll
    for (int o = 16; o; o >>= 1) part += __shfl_xor_sync(0xffffffffu, part, o);
    if (lane == 0) sm[ww] = part;
    __syncthreads();
    if (threadIdx.x == 0) {
        float s = 0.f;
        for (int i = 0; i < 8; i++) s += sm[i];
        g_partial[b * 256 + c] = s;
    }
}

// ---------------- kernel 6: loss finalize ------------------------------------
__global__ void k_loss(float* __restrict__ out) {
    __shared__ float sm[256];
    const int tid = threadIdx.x;
    float s = 0.f;
#pragma unroll
    for (int i = 0; i < 16; i++) s += g_partial[tid * 16 + i];
    sm[tid] = s;
    __syncthreads();
    for (int o = 128; o; o >>= 1) {
        if (tid < o) sm[tid] += sm[tid + o];
        __syncthreads();
    }
    if (tid == 0) {
        const float m = sm[0] / (float)ZQ_ELEMS;
        out[ZQ_ELEMS] = m + 0.25f * m;
    }
}

// ---------------- launcher ---------------------------------------------------
extern "C" void kernel_launch(void* const* d_in, const int* in_sizes, int n_in,
                              void* d_out, int out_size) {
    const float* z  = (const float*)d_in[0];
    const float* cb = (const float*)d_in[1];
    float* out = (float*)d_out;

    static int attr_set = 0;
    if (!attr_set) {
        cudaFuncSetAttribute(k_screen, cudaFuncAttributeMaxDynamicSharedMemorySize,
                             SMEM_TOTAL);
        attr_set = 1;
    }

    dim3 gT(32, 16);
    k_tz<<<gT, 256>>>(z);
    k_cbprep<<<1024, 256>>>(cb);
    k_screen<<<NSM, 512, SMEM_TOTAL>>>();
    k_rescore<<<N_ROWS / RROWS, 256>>>(cb, out + ZQ_ELEMS + 1);
    dim3 gG(256, 16);
    k_gather<<<gG, 256>>>(z, cb, out);
    k_loss<<<1, 256>>>(out);
}